// round 11
// baseline (speedup 1.0000x reference)
#include <cuda_runtime.h>
#include <cuda_fp16.h>
#include <cstdint>

#define NN    6000
#define FIN   300
#define HIDD  128
#define NH    8
#define ALPHAK 0.2f
#define NW 188             // ceil(6000/32)
#define CST 512            // fixed column stride per row (degree ~300, max < 400)

// ---------------- device scratch ----------------
__device__ __align__(256) __half g_Wh16[NN * NH * HIDD];   // [n][h][c]
__device__ __align__(256) __half g_x16[NN * 304];          // fp16 x, K padded
__device__ float    g_f1c[NH * NN];                        // [h][n]
__device__ float    g_f2c[NH * NN];                        // [h][n]
__device__ unsigned g_f2maxU[NH];
__device__ __align__(256) __half g_hcat16[NN * NH * HIDD];
__device__ float    g_Wh2part[4 * NN * HIDD];
__device__ __align__(256) __half g_Wh2h[NN * HIDD];
__device__ float    g_ao1[NH * HIDD];                      // W_out @ a_out[:128]
__device__ float    g_ao2[NH * HIDD];                      // W_out @ a_out[128:]
__device__ float    g_g1p[NH * NN];                        // per-head partial dots
__device__ float    g_g2p[NH * NN];
__device__ float    g_g1[NN];
__device__ float    g_g2[NN];
__device__ unsigned g_g2maxU[1];
__device__ int      g_deg[NN];
__device__ int      g_colsF[NN * CST];

// ordered-int float max encoding
__device__ __forceinline__ unsigned encf(float f) {
    int b = __float_as_int(f);
    return (b >= 0) ? ((unsigned)b | 0x80000000u) : (unsigned)(~b);
}
__device__ __forceinline__ float decf(unsigned k) {
    int b = (k & 0x80000000u) ? (int)(k & 0x7fffffffu) : ~(int)k;
    return __int_as_float(b);
}

// ---------------- one-pass CSR build: warp-per-row, fixed stride ----------------
__global__ __launch_bounds__(128) void csr_kernel(const float* __restrict__ adj) {
    int row  = blockIdx.x * 4 + (threadIdx.x >> 5);
    int lane = threadIdx.x & 31;
    if (row >= NN) return;
    const float* arow = adj + (size_t)row * NN;
    int* outp = g_colsF + row * CST;
    unsigned below = (1u << lane) - 1u;
    int cnt = 0;
    for (int w0 = 0; w0 < NW; w0++) {
        int col = w0 * 32 + lane;
        float v = (col < NN) ? arow[col] : 0.f;
        unsigned bits = __ballot_sync(0xffffffffu, v > 0.f);
        if ((bits >> lane) & 1u)
            outp[cnt + __popc(bits & below)] = col;
        cnt += __popc(bits);
    }
    if (lane == 0) g_deg[row] = cnt;
}

// ---------------- ao = W_out contracted with a_out (side stream) ----------------
__global__ __launch_bounds__(256) void ao_kernel(const float* __restrict__ W_out,
                                                 const float* __restrict__ a_out) {
    int wid = threadIdx.x >> 5, lane = threadIdx.x & 31;
    int k = blockIdx.x * 8 + wid;          // 0..1023
    float4 wv  = *(const float4*)(W_out + (size_t)k * HIDD + lane * 4);
    float4 a1v = *(const float4*)(a_out + lane * 4);
    float4 a2v = *(const float4*)(a_out + HIDD + lane * 4);
    float p1 = wv.x * a1v.x + wv.y * a1v.y + wv.z * a1v.z + wv.w * a1v.w;
    float p2 = wv.x * a2v.x + wv.y * a2v.y + wv.z * a2v.z + wv.w * a2v.w;
    #pragma unroll
    for (int o = 16; o; o >>= 1) {
        p1 += __shfl_down_sync(0xffffffffu, p1, o);
        p2 += __shfl_down_sync(0xffffffffu, p2, o);
    }
    if (lane == 0) { g_ao1[k] = p1; g_ao2[k] = p2; }
}

// ---------------- x -> fp16 padded (+ zero the max atomics) ----------------
__global__ __launch_bounds__(256) void x16_kernel(const float* __restrict__ x) {
    if (blockIdx.x == 0) {
        if (threadIdx.x < NH) g_f2maxU[threadIdx.x] = 0u;
        if (threadIdx.x == NH) g_g2maxU[0] = 0u;
    }
    int i = blockIdx.x * 256 + threadIdx.x;
    if (i >= NN * 304) return;
    int n = i / 304, c = i - n * 304;
    g_x16[i] = (c < FIN) ? __float2half_rn(x[(size_t)n * FIN + c]) : __ushort_as_half(0);
}

// ---------------- tensor-core fp16 GEMM, double-buffered ----------------
__device__ __forceinline__ void mma16816(float* c, const uint32_t* a, const uint32_t* b) {
    asm volatile(
        "mma.sync.aligned.m16n8k16.row.col.f32.f16.f16.f32 "
        "{%0,%1,%2,%3}, {%4,%5,%6,%7}, {%8,%9}, {%0,%1,%2,%3};\n"
        : "+f"(c[0]), "+f"(c[1]), "+f"(c[2]), "+f"(c[3])
        : "r"(a[0]), "r"(a[1]), "r"(a[2]), "r"(a[3]), "r"(b[0]), "r"(b[1]));
}

// MODE 0: g_Wh16 = x16 @ W_heads[sl]; epilogue computes f1/f2. grid (47, 8)
// MODE 1: g_Wh2part[sl] = hcat16[:, sl*256:(sl+1)*256] @ W_out[sl*256:,:]. grid (47, 2) x2
template <int MODE>
__global__ __launch_bounds__(256) void hgemm(const float* __restrict__ Bf,
                                             const float* __restrict__ a_heads,
                                             int yoff) {
    constexpr int NIT  = (MODE == 0) ? 19 : 16;   // K = 304 / 256
    constexpr int KVAL = (MODE == 0) ? FIN : 256;
    __shared__ __half As[2][128][18];
    __shared__ __half Bs[2][128][18];
    __shared__ float s1sh[128], s2sh[128];

    int tid  = threadIdx.x;
    int lane = tid & 31;
    int wid  = tid >> 5;
    int wm = wid & 3, wn = wid >> 2;
    int m0 = blockIdx.x * 128;
    int sl = blockIdx.y + yoff;
    const float*  Bg = Bf + (size_t)sl * ((MODE == 0) ? FIN * HIDD : 256 * HIDD);
    const __half* Ag = (MODE == 0) ? g_x16 : (g_hcat16 + sl * 256);
    const int lda = (MODE == 0) ? 304 : 1024;

    if (MODE == 0 && tid < 128) { s1sh[tid] = 0.f; s2sh[tid] = 0.f; }

    float acc[2][8][4];
    #pragma unroll
    for (int i = 0; i < 2; i++)
        #pragma unroll
        for (int j = 0; j < 8; j++)
            #pragma unroll
            for (int q = 0; q < 4; q++) acc[i][j][q] = 0.f;

    uint4  ph;
    float4 pb0, pb1;
    const float4 Z4 = make_float4(0.f, 0.f, 0.f, 0.f);

    int ar = tid >> 1, ahoff = (tid & 1) * 8;
    int bkr = tid >> 4, bc0 = (tid & 15) * 8;

    auto loadG = [&](int it) {
        int k0 = it * 16;
        int gr = m0 + ar;
        ph = (gr < NN) ? *(const uint4*)(Ag + (size_t)gr * lda + k0 + ahoff)
                       : make_uint4(0u, 0u, 0u, 0u);
        bool kok = (k0 + bkr) < KVAL;
        pb0 = kok ? *(const float4*)(Bg + (size_t)(k0 + bkr) * HIDD + bc0)     : Z4;
        pb1 = kok ? *(const float4*)(Bg + (size_t)(k0 + bkr) * HIDD + bc0 + 4) : Z4;
    };

    auto stS = [&](int buf) {
        *(uint32_t*)&As[buf][ar][ahoff]     = ph.x;
        *(uint32_t*)&As[buf][ar][ahoff + 2] = ph.y;
        *(uint32_t*)&As[buf][ar][ahoff + 4] = ph.z;
        *(uint32_t*)&As[buf][ar][ahoff + 6] = ph.w;
        Bs[buf][bc0 + 0][bkr] = __float2half_rn(pb0.x);
        Bs[buf][bc0 + 1][bkr] = __float2half_rn(pb0.y);
        Bs[buf][bc0 + 2][bkr] = __float2half_rn(pb0.z);
        Bs[buf][bc0 + 3][bkr] = __float2half_rn(pb0.w);
        Bs[buf][bc0 + 4][bkr] = __float2half_rn(pb1.x);
        Bs[buf][bc0 + 5][bkr] = __float2half_rn(pb1.y);
        Bs[buf][bc0 + 6][bkr] = __float2half_rn(pb1.z);
        Bs[buf][bc0 + 7][bkr] = __float2half_rn(pb1.w);
    };

    loadG(0);
    stS(0);
    __syncthreads();

    int r = lane >> 2, c2 = (lane & 3) * 2;
    for (int it = 0; it < NIT; it++) {
        int cur = it & 1;
        if (it + 1 < NIT) loadG(it + 1);

        uint32_t afr[2][4], bfr[8][2];
        #pragma unroll
        for (int mi = 0; mi < 2; mi++) {
            int row = wm * 32 + mi * 16 + r;
            afr[mi][0] = *(const uint32_t*)&As[cur][row][c2];
            afr[mi][1] = *(const uint32_t*)&As[cur][row + 8][c2];
            afr[mi][2] = *(const uint32_t*)&As[cur][row][c2 + 8];
            afr[mi][3] = *(const uint32_t*)&As[cur][row + 8][c2 + 8];
        }
        #pragma unroll
        for (int ni = 0; ni < 8; ni++) {
            int col = wn * 64 + ni * 8 + r;
            bfr[ni][0] = *(const uint32_t*)&Bs[cur][col][c2];
            bfr[ni][1] = *(const uint32_t*)&Bs[cur][col][c2 + 8];
        }
        #pragma unroll
        for (int mi = 0; mi < 2; mi++)
            #pragma unroll
            for (int ni = 0; ni < 8; ni++)
                mma16816(acc[mi][ni], afr[mi], bfr[ni]);

        if (it + 1 < NIT) stS(cur ^ 1);
        __syncthreads();
    }

    // store C
    #pragma unroll
    for (int mi = 0; mi < 2; mi++)
        #pragma unroll
        for (int hh = 0; hh < 2; hh++) {
            int row = m0 + wm * 32 + mi * 16 + r + hh * 8;
            if (row < NN) {
                #pragma unroll
                for (int ni = 0; ni < 8; ni++) {
                    int col = wn * 64 + ni * 8 + c2;
                    if (MODE == 0) {
                        *(__half2*)(g_Wh16 + (size_t)row * 1024 + sl * 128 + col) =
                            __float22half2_rn(make_float2(acc[mi][ni][hh * 2], acc[mi][ni][hh * 2 + 1]));
                    } else {
                        *(float2*)(g_Wh2part + (size_t)sl * NN * HIDD + (size_t)row * HIDD + col) =
                            make_float2(acc[mi][ni][hh * 2], acc[mi][ni][hh * 2 + 1]);
                    }
                }
            }
        }

    // fused f1/f2 epilogue (MODE 0)
    if (MODE == 0) {
        const float* a1 = a_heads + sl * 2 * HIDD;
        float p1[2][2] = {{0.f, 0.f}, {0.f, 0.f}};
        float p2[2][2] = {{0.f, 0.f}, {0.f, 0.f}};
        #pragma unroll
        for (int ni = 0; ni < 8; ni++) {
            int colb = wn * 64 + ni * 8 + c2;
            float a1x = a1[colb],        a1y = a1[colb + 1];
            float a2x = a1[HIDD + colb], a2y = a1[HIDD + colb + 1];
            #pragma unroll
            for (int mi = 0; mi < 2; mi++)
                #pragma unroll
                for (int hh = 0; hh < 2; hh++) {
                    p1[mi][hh] += acc[mi][ni][hh * 2] * a1x + acc[mi][ni][hh * 2 + 1] * a1y;
                    p2[mi][hh] += acc[mi][ni][hh * 2] * a2x + acc[mi][ni][hh * 2 + 1] * a2y;
                }
        }
        #pragma unroll
        for (int off = 1; off <= 2; off <<= 1)
            #pragma unroll
            for (int mi = 0; mi < 2; mi++)
                #pragma unroll
                for (int hh = 0; hh < 2; hh++) {
                    p1[mi][hh] += __shfl_xor_sync(0xffffffffu, p1[mi][hh], off);
                    p2[mi][hh] += __shfl_xor_sync(0xffffffffu, p2[mi][hh], off);
                }
        if ((lane & 3) == 0) {
            #pragma unroll
            for (int mi = 0; mi < 2; mi++)
                #pragma unroll
                for (int hh = 0; hh < 2; hh++) {
                    int rl = wm * 32 + mi * 16 + r + hh * 8;
                    atomicAdd(&s1sh[rl], p1[mi][hh]);
                    atomicAdd(&s2sh[rl], p2[mi][hh]);
                }
        }
        __syncthreads();
        if (tid < 128) {
            int row = m0 + tid;
            if (row < NN) {
                g_f1c[sl * NN + row] = s1sh[tid];
                g_f2c[sl * NN + row] = s2sh[tid];
                atomicMax(&g_f2maxU[sl], encf(s2sh[tid]));
            }
        }
    }
}

// ---------------- layer-1: warp-per-(node,head), 2-edge unrolled gather ----------
// grid (188, 4) x2 via h0 offset; 1024 threads.
__global__ __launch_bounds__(1024) void attn1_kernel(int h0) {
    int h = blockIdx.y + h0;
    int w = threadIdx.x >> 5, lane = threadIdx.x & 31;
    int row = blockIdx.x * 32 + w;
    if (row >= NN) return;
    float f1n   = g_f1c[h * NN + row];
    float shift = f1n + decf(g_f2maxU[h]);
    const float* __restrict__ f2p = g_f2c + h * NN;
    int beg = row * CST, end = beg + g_deg[row];
    const __half* Wl = g_Wh16 + h * 128 + lane * 4;

    float a0 = 0.f, a1 = 0.f, a2 = 0.f, a3 = 0.f, s = 0.f;

    for (int j0 = beg; j0 < end; j0 += 32) {
        int j = j0 + lane;
        int col = 0; float wgt = 0.f;
        if (j < end) {
            col = g_colsF[j];
            float v = f1n + f2p[col];
            v = (v > 0.f) ? v : ALPHAK * v;
            wgt = __expf(v - shift);
            s += wgt;
        }
        int lim = min(32, end - j0);
        int e = 0;
        for (; e + 1 < lim; e += 2) {
            float w0 = __shfl_sync(0xffffffffu, wgt, e);
            float w1 = __shfl_sync(0xffffffffu, wgt, e + 1);
            int   c0 = __shfl_sync(0xffffffffu, col, e);
            int   c1 = __shfl_sync(0xffffffffu, col, e + 1);
            uint2 d0 = __ldg((const uint2*)(Wl + (size_t)c0 * 1024));
            uint2 d1 = __ldg((const uint2*)(Wl + (size_t)c1 * 1024));
            float2 p0 = __half22float2(*(__half2*)&d0.x);
            float2 p1 = __half22float2(*(__half2*)&d0.y);
            float2 q0 = __half22float2(*(__half2*)&d1.x);
            float2 q1 = __half22float2(*(__half2*)&d1.y);
            a0 = fmaf(w0, p0.x, a0); a1 = fmaf(w0, p0.y, a1);
            a2 = fmaf(w0, p1.x, a2); a3 = fmaf(w0, p1.y, a3);
            a0 = fmaf(w1, q0.x, a0); a1 = fmaf(w1, q0.y, a1);
            a2 = fmaf(w1, q1.x, a2); a3 = fmaf(w1, q1.y, a3);
        }
        if (e < lim) {
            float w0 = __shfl_sync(0xffffffffu, wgt, e);
            int   c0 = __shfl_sync(0xffffffffu, col, e);
            uint2 d0 = __ldg((const uint2*)(Wl + (size_t)c0 * 1024));
            float2 p0 = __half22float2(*(__half2*)&d0.x);
            float2 p1 = __half22float2(*(__half2*)&d0.y);
            a0 = fmaf(w0, p0.x, a0); a1 = fmaf(w0, p0.y, a1);
            a2 = fmaf(w0, p1.x, a2); a3 = fmaf(w0, p1.y, a3);
        }
    }
    #pragma unroll
    for (int o = 16; o; o >>= 1) s += __shfl_xor_sync(0xffffffffu, s, o);
    float inv = 1.f / s;
    a0 *= inv; a1 *= inv; a2 *= inv; a3 *= inv;
    a0 = (a0 > 0.f) ? a0 : expm1f(a0);
    a1 = (a1 > 0.f) ? a1 : expm1f(a1);
    a2 = (a2 > 0.f) ? a2 : expm1f(a2);
    a3 = (a3 > 0.f) ? a3 : expm1f(a3);
    __half2 h0v = __float22half2_rn(make_float2(a0, a1));
    __half2 h1v = __float22half2_rn(make_float2(a2, a3));
    uint2 o2;
    o2.x = *reinterpret_cast<uint32_t*>(&h0v);
    o2.y = *reinterpret_cast<uint32_t*>(&h1v);
    *(uint2*)(g_hcat16 + (size_t)row * 1024 + h * 128 + lane * 4) = o2;

    // g1/g2 per-head partial dots with precomputed ao vectors (fp32 hcat)
    float4 o1v = *(const float4*)(g_ao1 + h * HIDD + lane * 4);
    float4 o2v = *(const float4*)(g_ao2 + h * HIDD + lane * 4);
    float p1 = a0 * o1v.x + a1 * o1v.y + a2 * o1v.z + a3 * o1v.w;
    float p2 = a0 * o2v.x + a1 * o2v.y + a2 * o2v.z + a3 * o2v.w;
    #pragma unroll
    for (int o = 16; o; o >>= 1) {
        p1 += __shfl_down_sync(0xffffffffu, p1, o);
        p2 += __shfl_down_sync(0xffffffffu, p2, o);
    }
    if (lane == 0) {
        g_g1p[h * NN + row] = p1;
        g_g2p[h * NN + row] = p2;
    }
}

// ---------------- g1/g2 final sum + g2max ----------------
__global__ __launch_bounds__(1024) void g12max_kernel() {
    int row = blockIdx.x * 1024 + threadIdx.x;
    if (row >= NN) return;
    float s1 = 0.f, s2 = 0.f;
    #pragma unroll
    for (int h = 0; h < NH; h++) {
        s1 += g_g1p[h * NN + row];
        s2 += g_g2p[h * NN + row];
    }
    g_g1[row] = s1;
    g_g2[row] = s2;
    atomicMax(&g_g2maxU[0], encf(s2));
}

// ---------------- combine split-K partials -> fp16 Wh2 ----------------
__global__ __launch_bounds__(1024) void combine4_kernel() {
    int idx = blockIdx.x * 1024 + threadIdx.x;
    if (idx >= NN * HIDD) return;
    float w = g_Wh2part[idx]
            + g_Wh2part[(size_t)NN * HIDD + idx]
            + g_Wh2part[(size_t)2 * NN * HIDD + idx]
            + g_Wh2part[(size_t)3 * NN * HIDD + idx];
    g_Wh2h[idx] = __float2half_rn(w);
}

// ---------------- layer-2: warp-per-node, 2-edge unrolled ----------------
__global__ __launch_bounds__(256) void attn2_kernel(float* __restrict__ dout) {
    int w = threadIdx.x >> 5, lane = threadIdx.x & 31;
    int row = blockIdx.x * 8 + w;
    if (row >= NN) return;
    float g1n   = g_g1[row];
    float shift = g1n + decf(g_g2maxU[0]);
    int beg = row * CST, end = beg + g_deg[row];
    const __half* Wl = g_Wh2h + lane * 4;

    float a0 = 0.f, a1 = 0.f, a2 = 0.f, a3 = 0.f, s = 0.f;

    for (int j0 = beg; j0 < end; j0 += 32) {
        int j = j0 + lane;
        int col = 0; float wgt = 0.f;
        if (j < end) {
            col = g_colsF[j];
            float v = g1n + g_g2[col];
            v = (v > 0.f) ? v : ALPHAK * v;
            wgt = __expf(v - shift);
            s += wgt;
        }
        int lim = min(32, end - j0);
        int e = 0;
        for (; e + 1 < lim; e += 2) {
            float w0 = __shfl_sync(0xffffffffu, wgt, e);
            float w1 = __shfl_sync(0xffffffffu, wgt, e + 1);
            int   c0 = __shfl_sync(0xffffffffu, col, e);
            int   c1 = __shfl_sync(0xffffffffu, col, e + 1);
            uint2 d0 = __ldg((const uint2*)(Wl + (size_t)c0 * 128));
            uint2 d1 = __ldg((const uint2*)(Wl + (size_t)c1 * 128));
            float2 p0 = __half22float2(*(__half2*)&d0.x);
            float2 p1 = __half22float2(*(__half2*)&d0.y);
            float2 q0 = __half22float2(*(__half2*)&d1.x);
            float2 q1 = __half22float2(*(__half2*)&d1.y);
            a0 = fmaf(w0, p0.x, a0); a1 = fmaf(w0, p0.y, a1);
            a2 = fmaf(w0, p1.x, a2); a3 = fmaf(w0, p1.y, a3);
            a0 = fmaf(w1, q0.x, a0); a1 = fmaf(w1, q0.y, a1);
            a2 = fmaf(w1, q1.x, a2); a3 = fmaf(w1, q1.y, a3);
        }
        if (e < lim) {
            float w0 = __shfl_sync(0xffffffffu, wgt, e);
            int   c0 = __shfl_sync(0xffffffffu, col, e);
            uint2 d0 = __ldg((const uint2*)(Wl + (size_t)c0 * 128));
            float2 p0 = __half22float2(*(__half2*)&d0.x);
            float2 p1 = __half22float2(*(__half2*)&d0.y);
            a0 = fmaf(w0, p0.x, a0); a1 = fmaf(w0, p0.y, a1);
            a2 = fmaf(w0, p1.x, a2); a3 = fmaf(w0, p1.y, a3);
        }
    }
    #pragma unroll
    for (int o = 16; o; o >>= 1) s += __shfl_xor_sync(0xffffffffu, s, o);
    float inv = 1.f / s;
    *(float4*)(dout + (size_t)row * HIDD + lane * 4) =
        make_float4(a0 * inv, a1 * inv, a2 * inv, a3 * inv);
}

// ---------------- launch ----------------
extern "C" void kernel_launch(void* const* d_in, const int* in_sizes, int n_in,
                              void* d_out, int out_size) {
    const float* x       = (const float*)d_in[0];
    const float* adj     = (const float*)d_in[1];
    const float* W_heads = (const float*)d_in[2];
    const float* a_heads = (const float*)d_in[3];
    const float* W_out   = (const float*)d_in[4];
    const float* a_out   = (const float*)d_in[5];
    float* out = (float*)d_out;

    // one-time setup (first call is the non-captured correctness run)
    static cudaStream_t s_side = nullptr;
    static cudaEvent_t evFork = nullptr, evCSR = nullptr, evA1 = nullptr,
                       evA2 = nullptr, evH = nullptr;
    if (s_side == nullptr) {
        cudaStreamCreateWithFlags(&s_side, cudaStreamNonBlocking);
        cudaEventCreateWithFlags(&evFork, cudaEventDisableTiming);
        cudaEventCreateWithFlags(&evCSR, cudaEventDisableTiming);
        cudaEventCreateWithFlags(&evA1, cudaEventDisableTiming);
        cudaEventCreateWithFlags(&evA2, cudaEventDisableTiming);
        cudaEventCreateWithFlags(&evH, cudaEventDisableTiming);
    }

    // fork: ao + one-pass CSR on side stream
    cudaEventRecord(evFork, 0);
    cudaStreamWaitEvent(s_side, evFork, 0);
    ao_kernel<<<128, 256, 0, s_side>>>(W_out, a_out);
    csr_kernel<<<1500, 128, 0, s_side>>>(adj);
    cudaEventRecord(evCSR, s_side);

    // main stream: dense phase (independent of CSR)
    x16_kernel<<<(NN * 304 + 255) / 256, 256>>>(x);
    hgemm<0><<<dim3(47, 8), 256>>>(W_heads, a_heads, 0);

    // join, then sparse layer-1 in two halves (heads 0-3, then 4-7)
    cudaStreamWaitEvent(0, evCSR, 0);
    attn1_kernel<<<dim3(188, 4), 1024>>>(0);
    cudaEventRecord(evA1, 0);
    attn1_kernel<<<dim3(188, 4), 1024>>>(4);
    cudaEventRecord(evA2, 0);

    // side stream: hgemm1 slices chase attn1 halves
    cudaStreamWaitEvent(s_side, evA1, 0);
    hgemm<1><<<dim3(47, 2), 256, 0, s_side>>>(W_out, nullptr, 0);
    cudaStreamWaitEvent(s_side, evA2, 0);
    hgemm<1><<<dim3(47, 2), 256, 0, s_side>>>(W_out, nullptr, 2);
    cudaEventRecord(evH, s_side);

    // main: g1/g2 finalize (overlaps side hgemm1b), then combine + layer-2
    g12max_kernel<<<6, 1024>>>();
    cudaStreamWaitEvent(0, evH, 0);
    combine4_kernel<<<750, 1024>>>();
    attn2_kernel<<<750, 256>>>(out);
}

// round 12
// speedup vs baseline: 1.0922x; 1.0922x over previous
#include <cuda_runtime.h>
#include <cuda_fp16.h>
#include <cstdint>

#define NN    6000
#define FIN   300
#define HIDD  128
#define NH    8
#define ALPHAK 0.2f
#define NW 188             // ceil(6000/32)
#define CST 512            // fixed column stride per row (degree ~300 + self)

// ---------------- device scratch ----------------
__device__ __align__(256) __half g_Wh16[NN * NH * HIDD];   // [n][h][c]
__device__ __align__(256) __half g_x16[NN * 304];          // fp16 x, K padded
__device__ float    g_f1c[NH * NN];                        // [h][n]
__device__ float    g_f2c[NH * NN];                        // [h][n]
__device__ unsigned g_f2maxU[NH];
__device__ __align__(256) __half g_hcat16[NN * NH * HIDD];
__device__ float    g_Wh2part[4 * NN * HIDD];
__device__ __align__(256) __half g_Wh2h[NN * HIDD];
__device__ float    g_ao1[NH * HIDD];                      // W_out @ a_out[:128]
__device__ float    g_ao2[NH * HIDD];                      // W_out @ a_out[128:]
__device__ float    g_g1p[NH * NN];                        // per-head partial dots
__device__ float    g_g2p[NH * NN];
__device__ float    g_g1[NN];
__device__ float    g_g2[NN];
__device__ unsigned g_g2maxU[1];
__device__ int      g_deg[NN];
__device__ int      g_colsF[NN * CST];

// ordered-int float max encoding
__device__ __forceinline__ unsigned encf(float f) {
    int b = __float_as_int(f);
    return (b >= 0) ? ((unsigned)b | 0x80000000u) : (unsigned)(~b);
}
__device__ __forceinline__ float decf(unsigned k) {
    int b = (k & 0x80000000u) ? (int)(k & 0x7fffffffu) : ~(int)k;
    return __int_as_float(b);
}

// ---------------- one-pass CSR build: warp-per-row, fixed stride ----------------
__global__ __launch_bounds__(128) void csr_kernel(const float* __restrict__ adj) {
    int row  = blockIdx.x * 4 + (threadIdx.x >> 5);
    int lane = threadIdx.x & 31;
    if (row >= NN) return;
    const float* arow = adj + (size_t)row * NN;
    int* outp = g_colsF + row * CST;
    unsigned below = (1u << lane) - 1u;
    int cnt = 0;
    for (int w0 = 0; w0 < NW; w0++) {
        int col = w0 * 32 + lane;
        float v = (col < NN) ? arow[col] : 0.f;
        unsigned bits = __ballot_sync(0xffffffffu, v > 0.f);
        if ((bits >> lane) & 1u)
            outp[cnt + __popc(bits & below)] = col;
        cnt += __popc(bits);
    }
    if (lane == 0) g_deg[row] = cnt;
}

// ---------------- ao = W_out contracted with a_out (side stream) ----------------
__global__ __launch_bounds__(256) void ao_kernel(const float* __restrict__ W_out,
                                                 const float* __restrict__ a_out) {
    int wid = threadIdx.x >> 5, lane = threadIdx.x & 31;
    int k = blockIdx.x * 8 + wid;          // 0..1023
    float4 wv  = *(const float4*)(W_out + (size_t)k * HIDD + lane * 4);
    float4 a1v = *(const float4*)(a_out + lane * 4);
    float4 a2v = *(const float4*)(a_out + HIDD + lane * 4);
    float p1 = wv.x * a1v.x + wv.y * a1v.y + wv.z * a1v.z + wv.w * a1v.w;
    float p2 = wv.x * a2v.x + wv.y * a2v.y + wv.z * a2v.z + wv.w * a2v.w;
    #pragma unroll
    for (int o = 16; o; o >>= 1) {
        p1 += __shfl_down_sync(0xffffffffu, p1, o);
        p2 += __shfl_down_sync(0xffffffffu, p2, o);
    }
    if (lane == 0) { g_ao1[k] = p1; g_ao2[k] = p2; }
}

// ---------------- x -> fp16 padded (+ zero the max atomics) ----------------
__global__ __launch_bounds__(256) void x16_kernel(const float* __restrict__ x) {
    if (blockIdx.x == 0) {
        if (threadIdx.x < NH) g_f2maxU[threadIdx.x] = 0u;
        if (threadIdx.x == NH) g_g2maxU[0] = 0u;
    }
    int i = blockIdx.x * 256 + threadIdx.x;
    if (i >= NN * 304) return;
    int n = i / 304, c = i - n * 304;
    g_x16[i] = (c < FIN) ? __float2half_rn(x[(size_t)n * FIN + c]) : __ushort_as_half(0);
}

// ---------------- tensor-core fp16 GEMM, double-buffered ----------------
__device__ __forceinline__ void mma16816(float* c, const uint32_t* a, const uint32_t* b) {
    asm volatile(
        "mma.sync.aligned.m16n8k16.row.col.f32.f16.f16.f32 "
        "{%0,%1,%2,%3}, {%4,%5,%6,%7}, {%8,%9}, {%0,%1,%2,%3};\n"
        : "+f"(c[0]), "+f"(c[1]), "+f"(c[2]), "+f"(c[3])
        : "r"(a[0]), "r"(a[1]), "r"(a[2]), "r"(a[3]), "r"(b[0]), "r"(b[1]));
}

// MODE 0: g_Wh16 = x16 @ W_heads[sl]; epilogue computes f1/f2. grid (47, 8)
// MODE 1: g_Wh2part[sl] = hcat16[:, sl*256:(sl+1)*256] @ W_out[sl*256:,:]. grid (47, 4)
template <int MODE>
__global__ __launch_bounds__(256) void hgemm(const float* __restrict__ Bf,
                                             const float* __restrict__ a_heads) {
    constexpr int NIT  = (MODE == 0) ? 19 : 16;   // K = 304 / 256
    constexpr int KVAL = (MODE == 0) ? FIN : 256;
    __shared__ __half As[2][128][18];
    __shared__ __half Bs[2][128][18];
    __shared__ float s1sh[128], s2sh[128];

    int tid  = threadIdx.x;
    int lane = tid & 31;
    int wid  = tid >> 5;
    int wm = wid & 3, wn = wid >> 2;
    int m0 = blockIdx.x * 128;
    int sl = blockIdx.y;
    const float*  Bg = Bf + (size_t)sl * ((MODE == 0) ? FIN * HIDD : 256 * HIDD);
    const __half* Ag = (MODE == 0) ? g_x16 : (g_hcat16 + sl * 256);
    const int lda = (MODE == 0) ? 304 : 1024;

    if (MODE == 0 && tid < 128) { s1sh[tid] = 0.f; s2sh[tid] = 0.f; }

    float acc[2][8][4];
    #pragma unroll
    for (int i = 0; i < 2; i++)
        #pragma unroll
        for (int j = 0; j < 8; j++)
            #pragma unroll
            for (int q = 0; q < 4; q++) acc[i][j][q] = 0.f;

    uint4  ph;
    float4 pb0, pb1;
    const float4 Z4 = make_float4(0.f, 0.f, 0.f, 0.f);

    int ar = tid >> 1, ahoff = (tid & 1) * 8;
    int bkr = tid >> 4, bc0 = (tid & 15) * 8;

    auto loadG = [&](int it) {
        int k0 = it * 16;
        int gr = m0 + ar;
        ph = (gr < NN) ? *(const uint4*)(Ag + (size_t)gr * lda + k0 + ahoff)
                       : make_uint4(0u, 0u, 0u, 0u);
        bool kok = (k0 + bkr) < KVAL;
        pb0 = kok ? *(const float4*)(Bg + (size_t)(k0 + bkr) * HIDD + bc0)     : Z4;
        pb1 = kok ? *(const float4*)(Bg + (size_t)(k0 + bkr) * HIDD + bc0 + 4) : Z4;
    };

    auto stS = [&](int buf) {
        *(uint32_t*)&As[buf][ar][ahoff]     = ph.x;
        *(uint32_t*)&As[buf][ar][ahoff + 2] = ph.y;
        *(uint32_t*)&As[buf][ar][ahoff + 4] = ph.z;
        *(uint32_t*)&As[buf][ar][ahoff + 6] = ph.w;
        Bs[buf][bc0 + 0][bkr] = __float2half_rn(pb0.x);
        Bs[buf][bc0 + 1][bkr] = __float2half_rn(pb0.y);
        Bs[buf][bc0 + 2][bkr] = __float2half_rn(pb0.z);
        Bs[buf][bc0 + 3][bkr] = __float2half_rn(pb0.w);
        Bs[buf][bc0 + 4][bkr] = __float2half_rn(pb1.x);
        Bs[buf][bc0 + 5][bkr] = __float2half_rn(pb1.y);
        Bs[buf][bc0 + 6][bkr] = __float2half_rn(pb1.z);
        Bs[buf][bc0 + 7][bkr] = __float2half_rn(pb1.w);
    };

    loadG(0);
    stS(0);
    __syncthreads();

    int r = lane >> 2, c2 = (lane & 3) * 2;
    for (int it = 0; it < NIT; it++) {
        int cur = it & 1;
        if (it + 1 < NIT) loadG(it + 1);

        uint32_t afr[2][4], bfr[8][2];
        #pragma unroll
        for (int mi = 0; mi < 2; mi++) {
            int row = wm * 32 + mi * 16 + r;
            afr[mi][0] = *(const uint32_t*)&As[cur][row][c2];
            afr[mi][1] = *(const uint32_t*)&As[cur][row + 8][c2];
            afr[mi][2] = *(const uint32_t*)&As[cur][row][c2 + 8];
            afr[mi][3] = *(const uint32_t*)&As[cur][row + 8][c2 + 8];
        }
        #pragma unroll
        for (int ni = 0; ni < 8; ni++) {
            int col = wn * 64 + ni * 8 + r;
            bfr[ni][0] = *(const uint32_t*)&Bs[cur][col][c2];
            bfr[ni][1] = *(const uint32_t*)&Bs[cur][col][c2 + 8];
        }
        #pragma unroll
        for (int mi = 0; mi < 2; mi++)
            #pragma unroll
            for (int ni = 0; ni < 8; ni++)
                mma16816(acc[mi][ni], afr[mi], bfr[ni]);

        if (it + 1 < NIT) stS(cur ^ 1);
        __syncthreads();
    }

    // store C
    #pragma unroll
    for (int mi = 0; mi < 2; mi++)
        #pragma unroll
        for (int hh = 0; hh < 2; hh++) {
            int row = m0 + wm * 32 + mi * 16 + r + hh * 8;
            if (row < NN) {
                #pragma unroll
                for (int ni = 0; ni < 8; ni++) {
                    int col = wn * 64 + ni * 8 + c2;
                    if (MODE == 0) {
                        *(__half2*)(g_Wh16 + (size_t)row * 1024 + sl * 128 + col) =
                            __float22half2_rn(make_float2(acc[mi][ni][hh * 2], acc[mi][ni][hh * 2 + 1]));
                    } else {
                        *(float2*)(g_Wh2part + (size_t)sl * NN * HIDD + (size_t)row * HIDD + col) =
                            make_float2(acc[mi][ni][hh * 2], acc[mi][ni][hh * 2 + 1]);
                    }
                }
            }
        }

    // fused f1/f2 epilogue (MODE 0)
    if (MODE == 0) {
        const float* a1 = a_heads + sl * 2 * HIDD;
        float p1[2][2] = {{0.f, 0.f}, {0.f, 0.f}};
        float p2[2][2] = {{0.f, 0.f}, {0.f, 0.f}};
        #pragma unroll
        for (int ni = 0; ni < 8; ni++) {
            int colb = wn * 64 + ni * 8 + c2;
            float a1x = a1[colb],        a1y = a1[colb + 1];
            float a2x = a1[HIDD + colb], a2y = a1[HIDD + colb + 1];
            #pragma unroll
            for (int mi = 0; mi < 2; mi++)
                #pragma unroll
                for (int hh = 0; hh < 2; hh++) {
                    p1[mi][hh] += acc[mi][ni][hh * 2] * a1x + acc[mi][ni][hh * 2 + 1] * a1y;
                    p2[mi][hh] += acc[mi][ni][hh * 2] * a2x + acc[mi][ni][hh * 2 + 1] * a2y;
                }
        }
        #pragma unroll
        for (int off = 1; off <= 2; off <<= 1)
            #pragma unroll
            for (int mi = 0; mi < 2; mi++)
                #pragma unroll
                for (int hh = 0; hh < 2; hh++) {
                    p1[mi][hh] += __shfl_xor_sync(0xffffffffu, p1[mi][hh], off);
                    p2[mi][hh] += __shfl_xor_sync(0xffffffffu, p2[mi][hh], off);
                }
        if ((lane & 3) == 0) {
            #pragma unroll
            for (int mi = 0; mi < 2; mi++)
                #pragma unroll
                for (int hh = 0; hh < 2; hh++) {
                    int rl = wm * 32 + mi * 16 + r + hh * 8;
                    atomicAdd(&s1sh[rl], p1[mi][hh]);
                    atomicAdd(&s2sh[rl], p2[mi][hh]);
                }
        }
        __syncthreads();
        if (tid < 128) {
            int row = m0 + tid;
            if (row < NN) {
                g_f1c[sl * NN + row] = s1sh[tid];
                g_f2c[sl * NN + row] = s2sh[tid];
                atomicMax(&g_f2maxU[sl], encf(s2sh[tid]));
            }
        }
    }
}

// ---------------- layer-1: warp-per-(node,head), 2-edge unrolled gather ----------
// grid (188, 8), 1024 threads (monolithic, proven config)
__global__ __launch_bounds__(1024) void attn1_kernel() {
    int h = blockIdx.y;
    int w = threadIdx.x >> 5, lane = threadIdx.x & 31;
    int row = blockIdx.x * 32 + w;
    if (row >= NN) return;
    float f1n   = g_f1c[h * NN + row];
    float shift = f1n + decf(g_f2maxU[h]);
    const float* __restrict__ f2p = g_f2c + h * NN;
    int beg = row * CST, end = beg + g_deg[row];
    const __half* Wl = g_Wh16 + h * 128 + lane * 4;

    float a0 = 0.f, a1 = 0.f, a2 = 0.f, a3 = 0.f, s = 0.f;

    for (int j0 = beg; j0 < end; j0 += 32) {
        int j = j0 + lane;
        int col = 0; float wgt = 0.f;
        if (j < end) {
            col = g_colsF[j];
            float v = f1n + f2p[col];
            v = (v > 0.f) ? v : ALPHAK * v;
            wgt = __expf(v - shift);
            s += wgt;
        }
        int lim = min(32, end - j0);
        int e = 0;
        for (; e + 1 < lim; e += 2) {
            float w0 = __shfl_sync(0xffffffffu, wgt, e);
            float w1 = __shfl_sync(0xffffffffu, wgt, e + 1);
            int   c0 = __shfl_sync(0xffffffffu, col, e);
            int   c1 = __shfl_sync(0xffffffffu, col, e + 1);
            uint2 d0 = __ldg((const uint2*)(Wl + (size_t)c0 * 1024));
            uint2 d1 = __ldg((const uint2*)(Wl + (size_t)c1 * 1024));
            float2 p0 = __half22float2(*(__half2*)&d0.x);
            float2 p1 = __half22float2(*(__half2*)&d0.y);
            float2 q0 = __half22float2(*(__half2*)&d1.x);
            float2 q1 = __half22float2(*(__half2*)&d1.y);
            a0 = fmaf(w0, p0.x, a0); a1 = fmaf(w0, p0.y, a1);
            a2 = fmaf(w0, p1.x, a2); a3 = fmaf(w0, p1.y, a3);
            a0 = fmaf(w1, q0.x, a0); a1 = fmaf(w1, q0.y, a1);
            a2 = fmaf(w1, q1.x, a2); a3 = fmaf(w1, q1.y, a3);
        }
        if (e < lim) {
            float w0 = __shfl_sync(0xffffffffu, wgt, e);
            int   c0 = __shfl_sync(0xffffffffu, col, e);
            uint2 d0 = __ldg((const uint2*)(Wl + (size_t)c0 * 1024));
            float2 p0 = __half22float2(*(__half2*)&d0.x);
            float2 p1 = __half22float2(*(__half2*)&d0.y);
            a0 = fmaf(w0, p0.x, a0); a1 = fmaf(w0, p0.y, a1);
            a2 = fmaf(w0, p1.x, a2); a3 = fmaf(w0, p1.y, a3);
        }
    }
    #pragma unroll
    for (int o = 16; o; o >>= 1) s += __shfl_xor_sync(0xffffffffu, s, o);
    float inv = 1.f / s;
    a0 *= inv; a1 *= inv; a2 *= inv; a3 *= inv;
    a0 = (a0 > 0.f) ? a0 : expm1f(a0);
    a1 = (a1 > 0.f) ? a1 : expm1f(a1);
    a2 = (a2 > 0.f) ? a2 : expm1f(a2);
    a3 = (a3 > 0.f) ? a3 : expm1f(a3);
    __half2 h0v = __float22half2_rn(make_float2(a0, a1));
    __half2 h1v = __float22half2_rn(make_float2(a2, a3));
    uint2 o2;
    o2.x = *reinterpret_cast<uint32_t*>(&h0v);
    o2.y = *reinterpret_cast<uint32_t*>(&h1v);
    *(uint2*)(g_hcat16 + (size_t)row * 1024 + h * 128 + lane * 4) = o2;

    // g1/g2 per-head partial dots with precomputed ao vectors (fp32 hcat)
    float4 o1v = *(const float4*)(g_ao1 + h * HIDD + lane * 4);
    float4 o2v = *(const float4*)(g_ao2 + h * HIDD + lane * 4);
    float p1 = a0 * o1v.x + a1 * o1v.y + a2 * o1v.z + a3 * o1v.w;
    float p2 = a0 * o2v.x + a1 * o2v.y + a2 * o2v.z + a3 * o2v.w;
    #pragma unroll
    for (int o = 16; o; o >>= 1) {
        p1 += __shfl_down_sync(0xffffffffu, p1, o);
        p2 += __shfl_down_sync(0xffffffffu, p2, o);
    }
    if (lane == 0) {
        g_g1p[h * NN + row] = p1;
        g_g2p[h * NN + row] = p2;
    }
}

// ---------------- g1/g2 final sum + g2max (side stream, overlaps hgemm1) ----------
__global__ __launch_bounds__(1024) void g12max_kernel() {
    int row = blockIdx.x * 1024 + threadIdx.x;
    if (row >= NN) return;
    float s1 = 0.f, s2 = 0.f;
    #pragma unroll
    for (int h = 0; h < NH; h++) {
        s1 += g_g1p[h * NN + row];
        s2 += g_g2p[h * NN + row];
    }
    g_g1[row] = s1;
    g_g2[row] = s2;
    atomicMax(&g_g2maxU[0], encf(s2));
}

// ---------------- combine split-K partials -> fp16 Wh2 ----------------
__global__ __launch_bounds__(1024) void combine4_kernel() {
    int idx = blockIdx.x * 1024 + threadIdx.x;
    if (idx >= NN * HIDD) return;
    float w = g_Wh2part[idx]
            + g_Wh2part[(size_t)NN * HIDD + idx]
            + g_Wh2part[(size_t)2 * NN * HIDD + idx]
            + g_Wh2part[(size_t)3 * NN * HIDD + idx];
    g_Wh2h[idx] = __float2half_rn(w);
}

// ---------------- layer-2: warp-per-node, 2-edge unrolled ----------------
__global__ __launch_bounds__(256) void attn2_kernel(float* __restrict__ dout) {
    int w = threadIdx.x >> 5, lane = threadIdx.x & 31;
    int row = blockIdx.x * 8 + w;
    if (row >= NN) return;
    float g1n   = g_g1[row];
    float shift = g1n + decf(g_g2maxU[0]);
    int beg = row * CST, end = beg + g_deg[row];
    const __half* Wl = g_Wh2h + lane * 4;

    float a0 = 0.f, a1 = 0.f, a2 = 0.f, a3 = 0.f, s = 0.f;

    for (int j0 = beg; j0 < end; j0 += 32) {
        int j = j0 + lane;
        int col = 0; float wgt = 0.f;
        if (j < end) {
            col = g_colsF[j];
            float v = g1n + g_g2[col];
            v = (v > 0.f) ? v : ALPHAK * v;
            wgt = __expf(v - shift);
            s += wgt;
        }
        int lim = min(32, end - j0);
        int e = 0;
        for (; e + 1 < lim; e += 2) {
            float w0 = __shfl_sync(0xffffffffu, wgt, e);
            float w1 = __shfl_sync(0xffffffffu, wgt, e + 1);
            int   c0 = __shfl_sync(0xffffffffu, col, e);
            int   c1 = __shfl_sync(0xffffffffu, col, e + 1);
            uint2 d0 = __ldg((const uint2*)(Wl + (size_t)c0 * 128));
            uint2 d1 = __ldg((const uint2*)(Wl + (size_t)c1 * 128));
            float2 p0 = __half22float2(*(__half2*)&d0.x);
            float2 p1 = __half22float2(*(__half2*)&d0.y);
            float2 q0 = __half22float2(*(__half2*)&d1.x);
            float2 q1 = __half22float2(*(__half2*)&d1.y);
            a0 = fmaf(w0, p0.x, a0); a1 = fmaf(w0, p0.y, a1);
            a2 = fmaf(w0, p1.x, a2); a3 = fmaf(w0, p1.y, a3);
            a0 = fmaf(w1, q0.x, a0); a1 = fmaf(w1, q0.y, a1);
            a2 = fmaf(w1, q1.x, a2); a3 = fmaf(w1, q1.y, a3);
        }
        if (e < lim) {
            float w0 = __shfl_sync(0xffffffffu, wgt, e);
            int   c0 = __shfl_sync(0xffffffffu, col, e);
            uint2 d0 = __ldg((const uint2*)(Wl + (size_t)c0 * 128));
            float2 p0 = __half22float2(*(__half2*)&d0.x);
            float2 p1 = __half22float2(*(__half2*)&d0.y);
            a0 = fmaf(w0, p0.x, a0); a1 = fmaf(w0, p0.y, a1);
            a2 = fmaf(w0, p1.x, a2); a3 = fmaf(w0, p1.y, a3);
        }
    }
    #pragma unroll
    for (int o = 16; o; o >>= 1) s += __shfl_xor_sync(0xffffffffu, s, o);
    float inv = 1.f / s;
    *(float4*)(dout + (size_t)row * HIDD + lane * 4) =
        make_float4(a0 * inv, a1 * inv, a2 * inv, a3 * inv);
}

// ---------------- launch ----------------
extern "C" void kernel_launch(void* const* d_in, const int* in_sizes, int n_in,
                              void* d_out, int out_size) {
    const float* x       = (const float*)d_in[0];
    const float* adj     = (const float*)d_in[1];
    const float* W_heads = (const float*)d_in[2];
    const float* a_heads = (const float*)d_in[3];
    const float* W_out   = (const float*)d_in[4];
    const float* a_out   = (const float*)d_in[5];
    float* out = (float*)d_out;

    // one-time setup (first call is the non-captured correctness run)
    static cudaStream_t s_side = nullptr;
    static cudaEvent_t evFork = nullptr, evCSR = nullptr, evA = nullptr, evG = nullptr;
    if (s_side == nullptr) {
        cudaStreamCreateWithFlags(&s_side, cudaStreamNonBlocking);
        cudaEventCreateWithFlags(&evFork, cudaEventDisableTiming);
        cudaEventCreateWithFlags(&evCSR, cudaEventDisableTiming);
        cudaEventCreateWithFlags(&evA, cudaEventDisableTiming);
        cudaEventCreateWithFlags(&evG, cudaEventDisableTiming);
    }

    // fork: ao + one-pass CSR on side stream (fits inside dense-phase shadow)
    cudaEventRecord(evFork, 0);
    cudaStreamWaitEvent(s_side, evFork, 0);
    ao_kernel<<<128, 256, 0, s_side>>>(W_out, a_out);
    csr_kernel<<<1500, 128, 0, s_side>>>(adj);
    cudaEventRecord(evCSR, s_side);

    // main stream: dense phase (independent of CSR)
    x16_kernel<<<(NN * 304 + 255) / 256, 256>>>(x);
    hgemm<0><<<dim3(47, 8), 256>>>(W_heads, a_heads);

    // join, then sparse layer-1 (monolithic; also emits g1/g2 partials)
    cudaStreamWaitEvent(0, evCSR, 0);
    attn1_kernel<<<dim3(188, NH), 1024>>>();
    cudaEventRecord(evA, 0);

    // side stream: finalize g1/g2 + g2max (overlaps hgemm1)
    cudaStreamWaitEvent(s_side, evA, 0);
    g12max_kernel<<<6, 1024, 0, s_side>>>();
    cudaEventRecord(evG, s_side);

    // main: layer-2 GEMM + combine, then attention
    hgemm<1><<<dim3(47, 4), 256>>>(W_out, nullptr);
    combine4_kernel<<<750, 1024>>>();
    cudaStreamWaitEvent(0, evG, 0);
    attn2_kernel<<<750, 256>>>(out);
}

// round 13
// speedup vs baseline: 1.1165x; 1.0222x over previous
#include <cuda_runtime.h>
#include <cuda_fp16.h>
#include <cstdint>

#define NN    6000
#define FIN   300
#define HIDD  128
#define NH    8
#define ALPHAK 0.2f
#define NW 188             // ceil(6000/32)
#define CST 512            // fixed column stride per row (degree ~300 + self)

// ---------------- device scratch ----------------
__device__ __align__(256) __half g_Wh16[NN * NH * HIDD];   // [n][h][c]
__device__ float    g_f1c[NH * NN];                        // [h][n]
__device__ float    g_f2c[NH * NN];                        // [h][n]
__device__ unsigned g_f2maxU[NH];                          // zero-init OK: encf(f) > 0u always
__device__ __align__(256) __half g_hcat16[NN * NH * HIDD];
__device__ float    g_Wh2part[4 * NN * HIDD];
__device__ __align__(256) __half g_Wh2h[NN * HIDD];
__device__ float    g_ao1[NH * HIDD];                      // W_out @ a_out[:128]
__device__ float    g_ao2[NH * HIDD];                      // W_out @ a_out[128:]
__device__ float    g_g1p[NH * NN];                        // per-head partial dots
__device__ float    g_g2p[NH * NN];
__device__ float    g_g1[NN];
__device__ float    g_g2[NN];
__device__ unsigned g_g2maxU[1];
__device__ int      g_deg[NN];
__device__ int      g_colsF[NN * CST];

// ordered-int float max encoding (note: encf(f) > 0 for ALL floats, so the
// zero-initialized atomic cells never win a max; values are replay-idempotent)
__device__ __forceinline__ unsigned encf(float f) {
    int b = __float_as_int(f);
    return (b >= 0) ? ((unsigned)b | 0x80000000u) : (unsigned)(~b);
}
__device__ __forceinline__ float decf(unsigned k) {
    int b = (k & 0x80000000u) ? (int)(k & 0x7fffffffu) : ~(int)k;
    return __int_as_float(b);
}

// ---------------- one-pass CSR build: warp-per-row, fixed stride ----------------
__global__ __launch_bounds__(128) void csr_kernel(const float* __restrict__ adj) {
    int row  = blockIdx.x * 4 + (threadIdx.x >> 5);
    int lane = threadIdx.x & 31;
    if (row >= NN) return;
    const float* arow = adj + (size_t)row * NN;
    int* outp = g_colsF + row * CST;
    unsigned below = (1u << lane) - 1u;
    int cnt = 0;
    for (int w0 = 0; w0 < NW; w0++) {
        int col = w0 * 32 + lane;
        float v = (col < NN) ? arow[col] : 0.f;
        unsigned bits = __ballot_sync(0xffffffffu, v > 0.f);
        if ((bits >> lane) & 1u)
            outp[cnt + __popc(bits & below)] = col;
        cnt += __popc(bits);
    }
    if (lane == 0) g_deg[row] = cnt;
}

// ---------------- ao = W_out contracted with a_out (side stream) ----------------
__global__ __launch_bounds__(256) void ao_kernel(const float* __restrict__ W_out,
                                                 const float* __restrict__ a_out) {
    int wid = threadIdx.x >> 5, lane = threadIdx.x & 31;
    int k = blockIdx.x * 8 + wid;          // 0..1023
    float4 wv  = *(const float4*)(W_out + (size_t)k * HIDD + lane * 4);
    float4 a1v = *(const float4*)(a_out + lane * 4);
    float4 a2v = *(const float4*)(a_out + HIDD + lane * 4);
    float p1 = wv.x * a1v.x + wv.y * a1v.y + wv.z * a1v.z + wv.w * a1v.w;
    float p2 = wv.x * a2v.x + wv.y * a2v.y + wv.z * a2v.z + wv.w * a2v.w;
    #pragma unroll
    for (int o = 16; o; o >>= 1) {
        p1 += __shfl_down_sync(0xffffffffu, p1, o);
        p2 += __shfl_down_sync(0xffffffffu, p2, o);
    }
    if (lane == 0) { g_ao1[k] = p1; g_ao2[k] = p2; }
}

// ---------------- tensor-core fp16 GEMM, double-buffered ----------------
__device__ __forceinline__ void mma16816(float* c, const uint32_t* a, const uint32_t* b) {
    asm volatile(
        "mma.sync.aligned.m16n8k16.row.col.f32.f16.f16.f32 "
        "{%0,%1,%2,%3}, {%4,%5,%6,%7}, {%8,%9}, {%0,%1,%2,%3};\n"
        : "+f"(c[0]), "+f"(c[1]), "+f"(c[2]), "+f"(c[3])
        : "r"(a[0]), "r"(a[1]), "r"(a[2]), "r"(a[3]), "r"(b[0]), "r"(b[1]));
}

// MODE 0: g_Wh16 = x(fp32, converted in-kernel) @ W_heads[sl]; epilogue computes f1/f2. grid (47, 8)
// MODE 1: g_Wh2part[sl] = hcat16[:, sl*256:(sl+1)*256] @ W_out[sl*256:,:]. grid (47, 4)
template <int MODE>
__global__ __launch_bounds__(256) void hgemm(const float* __restrict__ Bf,
                                             const float* __restrict__ a_heads,
                                             const float* __restrict__ Xf) {
    constexpr int NIT  = (MODE == 0) ? 19 : 16;   // K = 304 / 256
    constexpr int KVAL = (MODE == 0) ? FIN : 256;
    __shared__ __half As[2][128][18];
    __shared__ __half Bs[2][128][18];
    __shared__ float s1sh[128], s2sh[128];

    int tid  = threadIdx.x;
    int lane = tid & 31;
    int wid  = tid >> 5;
    int wm = wid & 3, wn = wid >> 2;
    int m0 = blockIdx.x * 128;
    int sl = blockIdx.y;
    const float*  Bg = Bf + (size_t)sl * ((MODE == 0) ? FIN * HIDD : 256 * HIDD);
    const __half* Ag = (MODE == 0) ? (const __half*)nullptr : (g_hcat16 + sl * 256);

    if (MODE == 0 && tid < 128) { s1sh[tid] = 0.f; s2sh[tid] = 0.f; }

    float acc[2][8][4];
    #pragma unroll
    for (int i = 0; i < 2; i++)
        #pragma unroll
        for (int j = 0; j < 8; j++)
            #pragma unroll
            for (int q = 0; q < 4; q++) acc[i][j][q] = 0.f;

    uint4  ph;
    float4 pa0, pa1, pb0, pb1;
    const float4 Z4 = make_float4(0.f, 0.f, 0.f, 0.f);

    int ar = tid >> 1, ahoff = (tid & 1) * 8;       // MODE 1 A-load
    int r0 = tid >> 2, coff = (tid & 3) * 4;        // MODE 0 A-load (fp32)
    int bkr = tid >> 4, bc0 = (tid & 15) * 8;

    auto loadG = [&](int it) {
        int k0 = it * 16;
        if (MODE == 0) {
            bool kok = (k0 + coff) < FIN;
            int gr0 = m0 + r0, gr1 = gr0 + 64;
            pa0 = (kok && gr0 < NN) ? *(const float4*)(Xf + (size_t)gr0 * FIN + k0 + coff) : Z4;
            pa1 = (kok && gr1 < NN) ? *(const float4*)(Xf + (size_t)gr1 * FIN + k0 + coff) : Z4;
        } else {
            int gr = m0 + ar;
            ph = (gr < NN) ? *(const uint4*)(Ag + (size_t)gr * 1024 + k0 + ahoff)
                           : make_uint4(0u, 0u, 0u, 0u);
        }
        bool kok2 = (k0 + bkr) < KVAL;
        pb0 = kok2 ? *(const float4*)(Bg + (size_t)(k0 + bkr) * HIDD + bc0)     : Z4;
        pb1 = kok2 ? *(const float4*)(Bg + (size_t)(k0 + bkr) * HIDD + bc0 + 4) : Z4;
    };

    auto stS = [&](int buf) {
        if (MODE == 0) {
            *(__half2*)&As[buf][r0][coff]          = __float22half2_rn(make_float2(pa0.x, pa0.y));
            *(__half2*)&As[buf][r0][coff + 2]      = __float22half2_rn(make_float2(pa0.z, pa0.w));
            *(__half2*)&As[buf][r0 + 64][coff]     = __float22half2_rn(make_float2(pa1.x, pa1.y));
            *(__half2*)&As[buf][r0 + 64][coff + 2] = __float22half2_rn(make_float2(pa1.z, pa1.w));
        } else {
            *(uint32_t*)&As[buf][ar][ahoff]     = ph.x;
            *(uint32_t*)&As[buf][ar][ahoff + 2] = ph.y;
            *(uint32_t*)&As[buf][ar][ahoff + 4] = ph.z;
            *(uint32_t*)&As[buf][ar][ahoff + 6] = ph.w;
        }
        Bs[buf][bc0 + 0][bkr] = __float2half_rn(pb0.x);
        Bs[buf][bc0 + 1][bkr] = __float2half_rn(pb0.y);
        Bs[buf][bc0 + 2][bkr] = __float2half_rn(pb0.z);
        Bs[buf][bc0 + 3][bkr] = __float2half_rn(pb0.w);
        Bs[buf][bc0 + 4][bkr] = __float2half_rn(pb1.x);
        Bs[buf][bc0 + 5][bkr] = __float2half_rn(pb1.y);
        Bs[buf][bc0 + 6][bkr] = __float2half_rn(pb1.z);
        Bs[buf][bc0 + 7][bkr] = __float2half_rn(pb1.w);
    };

    loadG(0);
    stS(0);
    __syncthreads();

    int r = lane >> 2, c2 = (lane & 3) * 2;
    for (int it = 0; it < NIT; it++) {
        int cur = it & 1;
        if (it + 1 < NIT) loadG(it + 1);

        uint32_t afr[2][4], bfr[8][2];
        #pragma unroll
        for (int mi = 0; mi < 2; mi++) {
            int row = wm * 32 + mi * 16 + r;
            afr[mi][0] = *(const uint32_t*)&As[cur][row][c2];
            afr[mi][1] = *(const uint32_t*)&As[cur][row + 8][c2];
            afr[mi][2] = *(const uint32_t*)&As[cur][row][c2 + 8];
            afr[mi][3] = *(const uint32_t*)&As[cur][row + 8][c2 + 8];
        }
        #pragma unroll
        for (int ni = 0; ni < 8; ni++) {
            int col = wn * 64 + ni * 8 + r;
            bfr[ni][0] = *(const uint32_t*)&Bs[cur][col][c2];
            bfr[ni][1] = *(const uint32_t*)&Bs[cur][col][c2 + 8];
        }
        #pragma unroll
        for (int mi = 0; mi < 2; mi++)
            #pragma unroll
            for (int ni = 0; ni < 8; ni++)
                mma16816(acc[mi][ni], afr[mi], bfr[ni]);

        if (it + 1 < NIT) stS(cur ^ 1);
        __syncthreads();
    }

    // store C
    #pragma unroll
    for (int mi = 0; mi < 2; mi++)
        #pragma unroll
        for (int hh = 0; hh < 2; hh++) {
            int row = m0 + wm * 32 + mi * 16 + r + hh * 8;
            if (row < NN) {
                #pragma unroll
                for (int ni = 0; ni < 8; ni++) {
                    int col = wn * 64 + ni * 8 + c2;
                    if (MODE == 0) {
                        *(__half2*)(g_Wh16 + (size_t)row * 1024 + sl * 128 + col) =
                            __float22half2_rn(make_float2(acc[mi][ni][hh * 2], acc[mi][ni][hh * 2 + 1]));
                    } else {
                        *(float2*)(g_Wh2part + (size_t)sl * NN * HIDD + (size_t)row * HIDD + col) =
                            make_float2(acc[mi][ni][hh * 2], acc[mi][ni][hh * 2 + 1]);
                    }
                }
            }
        }

    // fused f1/f2 epilogue (MODE 0)
    if (MODE == 0) {
        const float* a1 = a_heads + sl * 2 * HIDD;
        float p1[2][2] = {{0.f, 0.f}, {0.f, 0.f}};
        float p2[2][2] = {{0.f, 0.f}, {0.f, 0.f}};
        #pragma unroll
        for (int ni = 0; ni < 8; ni++) {
            int colb = wn * 64 + ni * 8 + c2;
            float a1x = a1[colb],        a1y = a1[colb + 1];
            float a2x = a1[HIDD + colb], a2y = a1[HIDD + colb + 1];
            #pragma unroll
            for (int mi = 0; mi < 2; mi++)
                #pragma unroll
                for (int hh = 0; hh < 2; hh++) {
                    p1[mi][hh] += acc[mi][ni][hh * 2] * a1x + acc[mi][ni][hh * 2 + 1] * a1y;
                    p2[mi][hh] += acc[mi][ni][hh * 2] * a2x + acc[mi][ni][hh * 2 + 1] * a2y;
                }
        }
        #pragma unroll
        for (int off = 1; off <= 2; off <<= 1)
            #pragma unroll
            for (int mi = 0; mi < 2; mi++)
                #pragma unroll
                for (int hh = 0; hh < 2; hh++) {
                    p1[mi][hh] += __shfl_xor_sync(0xffffffffu, p1[mi][hh], off);
                    p2[mi][hh] += __shfl_xor_sync(0xffffffffu, p2[mi][hh], off);
                }
        if ((lane & 3) == 0) {
            #pragma unroll
            for (int mi = 0; mi < 2; mi++)
                #pragma unroll
                for (int hh = 0; hh < 2; hh++) {
                    int rl = wm * 32 + mi * 16 + r + hh * 8;
                    atomicAdd(&s1sh[rl], p1[mi][hh]);
                    atomicAdd(&s2sh[rl], p2[mi][hh]);
                }
        }
        __syncthreads();
        if (tid < 128) {
            int row = m0 + tid;
            if (row < NN) {
                g_f1c[sl * NN + row] = s1sh[tid];
                g_f2c[sl * NN + row] = s2sh[tid];
                atomicMax(&g_f2maxU[sl], encf(s2sh[tid]));
            }
        }
    }
}

// ---------------- layer-1: warp-per-(node,head), 2-edge unrolled gather ----------
// grid (188, 8), 1024 threads (monolithic, proven config)
__global__ __launch_bounds__(1024) void attn1_kernel() {
    int h = blockIdx.y;
    int w = threadIdx.x >> 5, lane = threadIdx.x & 31;
    int row = blockIdx.x * 32 + w;
    if (row >= NN) return;
    float f1n   = g_f1c[h * NN + row];
    float shift = f1n + decf(g_f2maxU[h]);
    const float* __restrict__ f2p = g_f2c + h * NN;
    int beg = row * CST, end = beg + g_deg[row];
    const __half* Wl = g_Wh16 + h * 128 + lane * 4;

    float a0 = 0.f, a1 = 0.f, a2 = 0.f, a3 = 0.f, s = 0.f;

    for (int j0 = beg; j0 < end; j0 += 32) {
        int j = j0 + lane;
        int col = 0; float wgt = 0.f;
        if (j < end) {
            col = g_colsF[j];
            float v = f1n + f2p[col];
            v = (v > 0.f) ? v : ALPHAK * v;
            wgt = __expf(v - shift);
            s += wgt;
        }
        int lim = min(32, end - j0);
        int e = 0;
        for (; e + 1 < lim; e += 2) {
            float w0 = __shfl_sync(0xffffffffu, wgt, e);
            float w1 = __shfl_sync(0xffffffffu, wgt, e + 1);
            int   c0 = __shfl_sync(0xffffffffu, col, e);
            int   c1 = __shfl_sync(0xffffffffu, col, e + 1);
            uint2 d0 = __ldg((const uint2*)(Wl + (size_t)c0 * 1024));
            uint2 d1 = __ldg((const uint2*)(Wl + (size_t)c1 * 1024));
            float2 p0 = __half22float2(*(__half2*)&d0.x);
            float2 p1 = __half22float2(*(__half2*)&d0.y);
            float2 q0 = __half22float2(*(__half2*)&d1.x);
            float2 q1 = __half22float2(*(__half2*)&d1.y);
            a0 = fmaf(w0, p0.x, a0); a1 = fmaf(w0, p0.y, a1);
            a2 = fmaf(w0, p1.x, a2); a3 = fmaf(w0, p1.y, a3);
            a0 = fmaf(w1, q0.x, a0); a1 = fmaf(w1, q0.y, a1);
            a2 = fmaf(w1, q1.x, a2); a3 = fmaf(w1, q1.y, a3);
        }
        if (e < lim) {
            float w0 = __shfl_sync(0xffffffffu, wgt, e);
            int   c0 = __shfl_sync(0xffffffffu, col, e);
            uint2 d0 = __ldg((const uint2*)(Wl + (size_t)c0 * 1024));
            float2 p0 = __half22float2(*(__half2*)&d0.x);
            float2 p1 = __half22float2(*(__half2*)&d0.y);
            a0 = fmaf(w0, p0.x, a0); a1 = fmaf(w0, p0.y, a1);
            a2 = fmaf(w0, p1.x, a2); a3 = fmaf(w0, p1.y, a3);
        }
    }
    #pragma unroll
    for (int o = 16; o; o >>= 1) s += __shfl_xor_sync(0xffffffffu, s, o);
    float inv = 1.f / s;
    a0 *= inv; a1 *= inv; a2 *= inv; a3 *= inv;
    a0 = (a0 > 0.f) ? a0 : expm1f(a0);
    a1 = (a1 > 0.f) ? a1 : expm1f(a1);
    a2 = (a2 > 0.f) ? a2 : expm1f(a2);
    a3 = (a3 > 0.f) ? a3 : expm1f(a3);
    __half2 h0v = __float22half2_rn(make_float2(a0, a1));
    __half2 h1v = __float22half2_rn(make_float2(a2, a3));
    uint2 o2;
    o2.x = *reinterpret_cast<uint32_t*>(&h0v);
    o2.y = *reinterpret_cast<uint32_t*>(&h1v);
    *(uint2*)(g_hcat16 + (size_t)row * 1024 + h * 128 + lane * 4) = o2;

    // g1/g2 per-head partial dots with precomputed ao vectors (fp32 hcat)
    float4 o1v = *(const float4*)(g_ao1 + h * HIDD + lane * 4);
    float4 o2v = *(const float4*)(g_ao2 + h * HIDD + lane * 4);
    float p1 = a0 * o1v.x + a1 * o1v.y + a2 * o1v.z + a3 * o1v.w;
    float p2 = a0 * o2v.x + a1 * o2v.y + a2 * o2v.z + a3 * o2v.w;
    #pragma unroll
    for (int o = 16; o; o >>= 1) {
        p1 += __shfl_down_sync(0xffffffffu, p1, o);
        p2 += __shfl_down_sync(0xffffffffu, p2, o);
    }
    if (lane == 0) {
        g_g1p[h * NN + row] = p1;
        g_g2p[h * NN + row] = p2;
    }
}

// ---------------- g1/g2 final sum + g2max (side stream, overlaps hgemm1) ----------
__global__ __launch_bounds__(1024) void g12max_kernel() {
    int row = blockIdx.x * 1024 + threadIdx.x;
    if (row >= NN) return;
    float s1 = 0.f, s2 = 0.f;
    #pragma unroll
    for (int h = 0; h < NH; h++) {
        s1 += g_g1p[h * NN + row];
        s2 += g_g2p[h * NN + row];
    }
    g_g1[row] = s1;
    g_g2[row] = s2;
    atomicMax(&g_g2maxU[0], encf(s2));
}

// ---------------- combine split-K partials -> fp16 Wh2 ----------------
__global__ __launch_bounds__(1024) void combine4_kernel() {
    int idx = blockIdx.x * 1024 + threadIdx.x;
    if (idx >= NN * HIDD) return;
    float w = g_Wh2part[idx]
            + g_Wh2part[(size_t)NN * HIDD + idx]
            + g_Wh2part[(size_t)2 * NN * HIDD + idx]
            + g_Wh2part[(size_t)3 * NN * HIDD + idx];
    g_Wh2h[idx] = __float2half_rn(w);
}

// ---------------- layer-2: warp-per-node, 2-edge unrolled ----------------
__global__ __launch_bounds__(256) void attn2_kernel(float* __restrict__ dout) {
    int w = threadIdx.x >> 5, lane = threadIdx.x & 31;
    int row = blockIdx.x * 8 + w;
    if (row >= NN) return;
    float g1n   = g_g1[row];
    float shift = g1n + decf(g_g2maxU[0]);
    int beg = row * CST, end = beg + g_deg[row];
    const __half* Wl = g_Wh2h + lane * 4;

    float a0 = 0.f, a1 = 0.f, a2 = 0.f, a3 = 0.f, s = 0.f;

    for (int j0 = beg; j0 < end; j0 += 32) {
        int j = j0 + lane;
        int col = 0; float wgt = 0.f;
        if (j < end) {
            col = g_colsF[j];
            float v = g1n + g_g2[col];
            v = (v > 0.f) ? v : ALPHAK * v;
            wgt = __expf(v - shift);
            s += wgt;
        }
        int lim = min(32, end - j0);
        int e = 0;
        for (; e + 1 < lim; e += 2) {
            float w0 = __shfl_sync(0xffffffffu, wgt, e);
            float w1 = __shfl_sync(0xffffffffu, wgt, e + 1);
            int   c0 = __shfl_sync(0xffffffffu, col, e);
            int   c1 = __shfl_sync(0xffffffffu, col, e + 1);
            uint2 d0 = __ldg((const uint2*)(Wl + (size_t)c0 * 128));
            uint2 d1 = __ldg((const uint2*)(Wl + (size_t)c1 * 128));
            float2 p0 = __half22float2(*(__half2*)&d0.x);
            float2 p1 = __half22float2(*(__half2*)&d0.y);
            float2 q0 = __half22float2(*(__half2*)&d1.x);
            float2 q1 = __half22float2(*(__half2*)&d1.y);
            a0 = fmaf(w0, p0.x, a0); a1 = fmaf(w0, p0.y, a1);
            a2 = fmaf(w0, p1.x, a2); a3 = fmaf(w0, p1.y, a3);
            a0 = fmaf(w1, q0.x, a0); a1 = fmaf(w1, q0.y, a1);
            a2 = fmaf(w1, q1.x, a2); a3 = fmaf(w1, q1.y, a3);
        }
        if (e < lim) {
            float w0 = __shfl_sync(0xffffffffu, wgt, e);
            int   c0 = __shfl_sync(0xffffffffu, col, e);
            uint2 d0 = __ldg((const uint2*)(Wl + (size_t)c0 * 128));
            float2 p0 = __half22float2(*(__half2*)&d0.x);
            float2 p1 = __half22float2(*(__half2*)&d0.y);
            a0 = fmaf(w0, p0.x, a0); a1 = fmaf(w0, p0.y, a1);
            a2 = fmaf(w0, p1.x, a2); a3 = fmaf(w0, p1.y, a3);
        }
    }
    #pragma unroll
    for (int o = 16; o; o >>= 1) s += __shfl_xor_sync(0xffffffffu, s, o);
    float inv = 1.f / s;
    *(float4*)(dout + (size_t)row * HIDD + lane * 4) =
        make_float4(a0 * inv, a1 * inv, a2 * inv, a3 * inv);
}

// ---------------- launch ----------------
extern "C" void kernel_launch(void* const* d_in, const int* in_sizes, int n_in,
                              void* d_out, int out_size) {
    const float* x       = (const float*)d_in[0];
    const float* adj     = (const float*)d_in[1];
    const float* W_heads = (const float*)d_in[2];
    const float* a_heads = (const float*)d_in[3];
    const float* W_out   = (const float*)d_in[4];
    const float* a_out   = (const float*)d_in[5];
    float* out = (float*)d_out;

    // one-time setup (first call is the non-captured correctness run)
    static cudaStream_t s_side = nullptr;
    static cudaEvent_t evFork = nullptr, evCSR = nullptr, evA = nullptr, evG = nullptr;
    if (s_side == nullptr) {
        cudaStreamCreateWithFlags(&s_side, cudaStreamNonBlocking);
        cudaEventCreateWithFlags(&evFork, cudaEventDisableTiming);
        cudaEventCreateWithFlags(&evCSR, cudaEventDisableTiming);
        cudaEventCreateWithFlags(&evA, cudaEventDisableTiming);
        cudaEventCreateWithFlags(&evG, cudaEventDisableTiming);
    }

    // fork: ao + one-pass CSR on side stream (fits inside hgemm0's shadow)
    cudaEventRecord(evFork, 0);
    cudaStreamWaitEvent(s_side, evFork, 0);
    ao_kernel<<<128, 256, 0, s_side>>>(W_out, a_out);
    csr_kernel<<<1500, 128, 0, s_side>>>(adj);
    cudaEventRecord(evCSR, s_side);

    // main stream: dense phase starts immediately (fp32 x read in-kernel)
    hgemm<0><<<dim3(47, 8), 256>>>(W_heads, a_heads, x);

    // join, then sparse layer-1 (monolithic; also emits g1/g2 partials)
    cudaStreamWaitEvent(0, evCSR, 0);
    attn1_kernel<<<dim3(188, NH), 1024>>>();
    cudaEventRecord(evA, 0);

    // side stream: finalize g1/g2 + g2max (overlaps hgemm1)
    cudaStreamWaitEvent(s_side, evA, 0);
    g12max_kernel<<<6, 1024, 0, s_side>>>();
    cudaEventRecord(evG, s_side);

    // main: layer-2 GEMM + combine, then attention
    hgemm<1><<<dim3(47, 4), 256>>>(W_out, nullptr, nullptr);
    combine4_kernel<<<750, 1024>>>();
    cudaStreamWaitEvent(0, evG, 0);
    attn2_kernel<<<750, 256>>>(out);
}